// round 2
// baseline (speedup 1.0000x reference)
#include <cuda_runtime.h>
#include <cstddef>
#include <cstdint>

#define NN 20000      // nodes
#define NE 50000      // edges
#define NB 1024       // graphs
#define DIN 32
#define H 64

// ---------------- scratch (static device globals; no allocation) ----------------
__device__ float g_out[NN * H];                    // node features (out == h)
__device__ float g_z[NE * H];                      // edge hidden
__device__ float g_ew[(size_t)NE * H * H];         // per-edge weight matrices (819 MB)
__device__ float g_agg[NN * H];
__device__ float g_m[NN * H];
__device__ float g_gi[NN * 3 * H];
__device__ float g_gh[NN * 3 * H];
__device__ float g_qh[NB * H];
__device__ float g_qc[NB * H];
__device__ float g_qstar[NB * 2 * H];
__device__ float g_g[NB * 4 * H];
__device__ float g_e[NN];
__device__ float g_emax[NB];
__device__ float g_asum[NB];
__device__ float g_feat[NB * 130];
__device__ float g_y1[NB * H];
__device__ float g_y2[NB * H];

__device__ __forceinline__ float sigf(float x) { return 1.f / (1.f + __expf(-x)); }

__device__ __forceinline__ float atomicMaxFloat(float* addr, float value) {
    if (value >= 0.f)
        return __int_as_float(atomicMax((int*)addr, __float_as_int(value)));
    else
        return __uint_as_float(atomicMin((unsigned int*)addr, __float_as_uint(value)));
}

// ---------------- generic fp32 GEMM: C[M,Nn] = A[M,K] * B (+bias +add, relu) ----------
// flags bit0: B is stored transposed as W[Nn,K] (C = A @ W^T); bit1: relu epilogue
#define BM 128
#define BN 128
#define BK 64
#define ALD 68    // As row stride (As[BM][ALD])
#define BLD 132   // Bs row stride (Bs[BK][BLD])
#define GEMM_SMEM ((BM * ALD + BK * BLD) * 4)

__global__ __launch_bounds__(256)
void gemm_k(const float* __restrict__ A, const float* __restrict__ B,
            const float* __restrict__ bias, const float* __restrict__ add,
            float* __restrict__ C, int M, int Nn, int K, int flags)
{
    extern __shared__ float sm[];
    float* As = sm;               // [BM][ALD], layout As[m][k]
    float* Bs = sm + BM * ALD;    // [BK][BLD], layout Bs[k][n]

    const bool bt = flags & 1;
    const bool dorelu = flags & 2;

    int tid = threadIdx.x;
    int m0 = blockIdx.y * BM, n0 = blockIdx.x * BN;
    int tx = tid & 15, ty = tid >> 4;
    int tm = ty * 8, tn = tx * 8;

    float acc[8][8];
#pragma unroll
    for (int i = 0; i < 8; i++)
#pragma unroll
        for (int j = 0; j < 8; j++) acc[i][j] = 0.f;

    for (int k0 = 0; k0 < K; k0 += BK) {
        // load A tile: 8192 elems, 32/thread; coalesced on k; conflict-free smem writes
#pragma unroll
        for (int i = 0; i < 32; i++) {
            int lin = i * 256 + tid;
            int m = lin >> 6, k = lin & 63;
            int gm = m0 + m, gk = k0 + k;
            As[m * ALD + k] = (gm < M && gk < K) ? A[(size_t)gm * K + gk] : 0.f;
        }
        if (!bt) {
#pragma unroll
            for (int i = 0; i < 32; i++) {
                int lin = i * 256 + tid;
                int k = lin >> 7, n = lin & 127;
                int gk = k0 + k, gn = n0 + n;
                Bs[k * BLD + n] = (gk < K && gn < Nn) ? B[(size_t)gk * Nn + gn] : 0.f;
            }
        } else {
#pragma unroll
            for (int i = 0; i < 32; i++) {
                int lin = i * 256 + tid;
                int n = lin >> 6, k = lin & 63;
                int gk = k0 + k, gn = n0 + n;
                Bs[k * BLD + n] = (gk < K && gn < Nn) ? B[(size_t)gn * K + gk] : 0.f;
            }
        }
        __syncthreads();

#pragma unroll 8
        for (int k = 0; k < BK; k++) {
            float a[8], b[8];
#pragma unroll
            for (int i = 0; i < 8; i++) a[i] = As[(tm + i) * ALD + k];
            float4 bv0 = *(const float4*)&Bs[k * BLD + tn];
            float4 bv1 = *(const float4*)&Bs[k * BLD + tn + 4];
            b[0] = bv0.x; b[1] = bv0.y; b[2] = bv0.z; b[3] = bv0.w;
            b[4] = bv1.x; b[5] = bv1.y; b[6] = bv1.z; b[7] = bv1.w;
#pragma unroll
            for (int i = 0; i < 8; i++)
#pragma unroll
                for (int j = 0; j < 8; j++) acc[i][j] = fmaf(a[i], b[j], acc[i][j]);
        }
        __syncthreads();
    }

#pragma unroll
    for (int i = 0; i < 8; i++) {
        int gm = m0 + tm + i;
        if (gm >= M) continue;
#pragma unroll
        for (int j = 0; j < 8; j++) {
            int gn = n0 + tn + j;
            if (gn >= Nn) continue;
            float v = acc[i][j];
            if (bias) v += bias[gn];
            if (add)  v += add[(size_t)gm * Nn + gn];
            if (dorelu) v = fmaxf(v, 0.f);
            C[(size_t)gm * Nn + gn] = v;
        }
    }
}

// ---------------- misc kernels ----------------
__global__ void zero_k(float* p, int n) {
    int i = blockIdx.x * 256 + threadIdx.x;
    if (i < n) p[i] = 0.f;
}

// per-edge: msg[e] = out[src[e]] (1xH) @ ew[e] (HxH); atomic scatter into agg[dst[e]]
__global__ void einsum_scatter(const int* __restrict__ ei) {
    __shared__ float s[4][H];
    int e = blockIdx.x * 4 + threadIdx.y;
    int o = threadIdx.x;
    if (e < NE) {
        int src = ei[e];
        s[threadIdx.y][o] = g_out[src * H + o];
    }
    __syncthreads();
    if (e >= NE) return;
    const float* w = g_ew + (size_t)e * (H * H) + o;
    float acc = 0.f;
#pragma unroll
    for (int h2 = 0; h2 < H; h2++) acc = fmaf(s[threadIdx.y][h2], w[h2 * H], acc);
    int dst = ei[NE + e];
    atomicAdd(&g_agg[dst * H + o], acc);
}

__global__ void gru_gate_k() {
    int idx = blockIdx.x * 256 + threadIdx.x;
    if (idx >= NN * H) return;
    int n = idx >> 6, j = idx & 63;
    const float* gi = g_gi + n * (3 * H);
    const float* gh = g_gh + n * (3 * H);
    float r = sigf(gi[j] + gh[j]);
    float z = sigf(gi[H + j] + gh[H + j]);
    float nn = tanhf(gi[2 * H + j] + r * gh[2 * H + j]);
    float h = g_out[idx];
    g_out[idx] = (1.f - z) * nn + z * h;
}

__global__ void lstm_gate_k() {
    int idx = blockIdx.x * 256 + threadIdx.x;
    if (idx >= NB * H) return;
    int b = idx >> 6, j = idx & 63;
    const float* gr = g_g + b * (4 * H);
    float ig = sigf(gr[j]);
    float fg = sigf(gr[H + j]);
    float gg = tanhf(gr[2 * H + j]);
    float og = sigf(gr[3 * H + j]);
    float c = fg * g_qc[idx] + ig * gg;
    g_qc[idx] = c;
    float hh = og * tanhf(c);
    g_qh[idx] = hh;
    g_qstar[b * (2 * H) + j] = hh;   // q part of q_star
}

__global__ void s2s_init_k() {
    int idx = blockIdx.x * 256 + threadIdx.x;
    if (idx >= NB * H) return;
    int b = idx >> 6, j = idx & 63;
    g_qstar[b * (2 * H) + H + j] = 0.f;   // r_ accumulator
    if (j == 0) { g_emax[b] = -1e30f; g_asum[b] = 0.f; }
}

__global__ void attn_e_max_k(const int* __restrict__ batch) {
    int n = blockIdx.x * 256 + threadIdx.x;
    if (n >= NN) return;
    int b = batch[n];
    const float* o = g_out + n * H;
    const float* q = g_qh + b * H;
    float acc = 0.f;
#pragma unroll
    for (int j = 0; j < H; j++) acc = fmaf(o[j], q[j], acc);
    g_e[n] = acc;
    atomicMaxFloat(&g_emax[b], acc);
}

__global__ void attn_exp_k(const int* __restrict__ batch) {
    int n = blockIdx.x * 256 + threadIdx.x;
    if (n >= NN) return;
    int b = batch[n];
    float a = __expf(g_e[n] - g_emax[b]);
    g_e[n] = a;
    atomicAdd(&g_asum[b], a);
}

__global__ void attn_scatter_k(const int* __restrict__ batch) {
    int n = blockIdx.x * 4 + threadIdx.y;
    int j = threadIdx.x;
    if (n >= NN) return;
    int b = batch[n];
    float coeff = g_e[n] / g_asum[b];
    atomicAdd(&g_qstar[b * (2 * H) + H + j], coeff * g_out[n * H + j]);
}

__global__ void feat_k(const float* __restrict__ t, const float* __restrict__ p) {
    int idx = blockIdx.x * 256 + threadIdx.x;
    if (idx >= NB * 130) return;
    int b = idx / 130, c = idx - b * 130;
    float v;
    if (c < 128) v = g_qstar[b * 128 + c];
    else if (c == 128) v = t[b];
    else v = p[b];
    g_feat[idx] = v;
}

__global__ void final_k(const float* __restrict__ W3, const float* __restrict__ b3,
                        float* __restrict__ out) {
    int b = blockIdx.x * 256 + threadIdx.x;
    if (b >= NB) return;
    float acc = b3[0];
#pragma unroll
    for (int j = 0; j < H; j++) acc = fmaf(g_y2[b * H + j], W3[j], acc);
    out[b] = acc;
}

// ---------------- host ----------------
static void launch_gemm(const float* A, const float* B, const float* bias,
                        const float* add, float* C, int M, int Nn, int K, int flags) {
    dim3 grid((Nn + BN - 1) / BN, (M + BM - 1) / BM);
    gemm_k<<<grid, 256, GEMM_SMEM>>>(A, B, bias, add, C, M, Nn, K, flags);
}

static void launch_zero(float* p, int n) {
    zero_k<<<(n + 255) / 256, 256>>>(p, n);
}

extern "C" void kernel_launch(void* const* d_in, const int* in_sizes, int n_in,
                              void* d_out, int out_size)
{
    // ---- resolve input ordering ----
    const float *x, *ea, *t, *p;
    const float *W0, *b0, *We1, *be1, *We2, *be2, *Wroot, *bconv;
    const float *wih, *whh, *bih, *bhh, *lwih, *lwhh, *lbih, *lbhh;
    const float *W1, *b1, *W2, *b2, *W3, *b3;
    const int *ei, *batch;

    bool dictOrder = (in_sizes[1] == 2 * NE);   // edge_index in slot 1 => dict order
    if (dictOrder) {
        x = (const float*)d_in[0];
        ei = (const int*)d_in[1];
        ea = (const float*)d_in[2];
        batch = (const int*)d_in[3];
        t = (const float*)d_in[4];
        p = (const float*)d_in[5];
        int w = (in_sizes[6] == 1) ? 7 : 6;     // skip num_graphs scalar if present
        W0 = (const float*)d_in[w + 0];  b0 = (const float*)d_in[w + 1];
        We1 = (const float*)d_in[w + 2]; be1 = (const float*)d_in[w + 3];
        We2 = (const float*)d_in[w + 4]; be2 = (const float*)d_in[w + 5];
        Wroot = (const float*)d_in[w + 6]; bconv = (const float*)d_in[w + 7];
        wih = (const float*)d_in[w + 8];  whh = (const float*)d_in[w + 9];
        bih = (const float*)d_in[w + 10]; bhh = (const float*)d_in[w + 11];
        lwih = (const float*)d_in[w + 12]; lwhh = (const float*)d_in[w + 13];
        lbih = (const float*)d_in[w + 14]; lbhh = (const float*)d_in[w + 15];
        W1 = (const float*)d_in[w + 16]; b1 = (const float*)d_in[w + 17];
        W2 = (const float*)d_in[w + 18]; b2 = (const float*)d_in[w + 19];
        W3 = (const float*)d_in[w + 20]; b3 = (const float*)d_in[w + 21];
    } else {
        // reference-argument order, edge_index/batch/num_graphs trailing
        x = (const float*)d_in[0];
        ea = (const float*)d_in[1];
        t = (const float*)d_in[2];
        p = (const float*)d_in[3];
        W0 = (const float*)d_in[4];  b0 = (const float*)d_in[5];
        We1 = (const float*)d_in[6]; be1 = (const float*)d_in[7];
        We2 = (const float*)d_in[8]; be2 = (const float*)d_in[9];
        Wroot = (const float*)d_in[10]; bconv = (const float*)d_in[11];
        wih = (const float*)d_in[12]; whh = (const float*)d_in[13];
        bih = (const float*)d_in[14]; bhh = (const float*)d_in[15];
        lwih = (const float*)d_in[16]; lwhh = (const float*)d_in[17];
        lbih = (const float*)d_in[18]; lbhh = (const float*)d_in[19];
        W1 = (const float*)d_in[20]; b1 = (const float*)d_in[21];
        W2 = (const float*)d_in[22]; b2 = (const float*)d_in[23];
        W3 = (const float*)d_in[24]; b3 = (const float*)d_in[25];
        ei = (const int*)d_in[26];
        batch = (const int*)d_in[27];
    }

    // ---- scratch addresses ----
    float *p_out, *p_z, *p_ew, *p_agg, *p_m, *p_gi, *p_gh;
    float *p_qh, *p_qc, *p_qstar, *p_g, *p_feat, *p_y1, *p_y2;
    cudaGetSymbolAddress((void**)&p_out, g_out);
    cudaGetSymbolAddress((void**)&p_z, g_z);
    cudaGetSymbolAddress((void**)&p_ew, g_ew);
    cudaGetSymbolAddress((void**)&p_agg, g_agg);
    cudaGetSymbolAddress((void**)&p_m, g_m);
    cudaGetSymbolAddress((void**)&p_gi, g_gi);
    cudaGetSymbolAddress((void**)&p_gh, g_gh);
    cudaGetSymbolAddress((void**)&p_qh, g_qh);
    cudaGetSymbolAddress((void**)&p_qc, g_qc);
    cudaGetSymbolAddress((void**)&p_qstar, g_qstar);
    cudaGetSymbolAddress((void**)&p_g, g_g);
    cudaGetSymbolAddress((void**)&p_feat, g_feat);
    cudaGetSymbolAddress((void**)&p_y1, g_y1);
    cudaGetSymbolAddress((void**)&p_y2, g_y2);

    cudaFuncSetAttribute(gemm_k, cudaFuncAttributeMaxDynamicSharedMemorySize, GEMM_SMEM);

    // ---- 1. input linear + edge MLP ----
    launch_gemm(x, W0, b0, nullptr, p_out, NN, H, DIN, 2);          // out = relu(x@W0+b0)
    launch_gemm(ea, We1, be1, nullptr, p_z, NE, H, 6, 2);           // z = relu(ea@We1+be1)
    launch_gemm(p_z, We2, be2, nullptr, p_ew, NE, H * H, H, 0);     // ew = z@We2+be2

    // ---- 2. 4x (NNConv + GRU) ----
    for (int it = 0; it < 4; it++) {
        launch_zero(p_agg, NN * H);
        einsum_scatter<<<NE / 4, dim3(H, 4)>>>(ei);
        launch_gemm(p_out, Wroot, bconv, p_agg, p_m, NN, H, H, 2);          // m = relu(agg + out@Wroot + bconv)
        launch_gemm(p_m, wih, bih, nullptr, p_gi, NN, 3 * H, H, 1);         // gi = m @ Wih^T + bih
        launch_gemm(p_out, whh, bhh, nullptr, p_gh, NN, 3 * H, H, 1);       // gh = h @ Whh^T + bhh
        gru_gate_k<<<(NN * H + 255) / 256, 256>>>();
    }

    // ---- 3. Set2Set (3 steps) ----
    launch_zero(p_qh, NB * H);
    launch_zero(p_qc, NB * H);
    launch_zero(p_qstar, NB * 2 * H);
    for (int st = 0; st < 3; st++) {
        launch_gemm(p_qstar, lwih, lbih, nullptr, p_g, NB, 4 * H, 2 * H, 1);
        launch_gemm(p_qh, lwhh, lbhh, p_g, p_g, NB, 4 * H, H, 1);
        lstm_gate_k<<<(NB * H + 255) / 256, 256>>>();
        s2s_init_k<<<(NB * H + 255) / 256, 256>>>();
        attn_e_max_k<<<(NN + 255) / 256, 256>>>(batch);
        attn_exp_k<<<(NN + 255) / 256, 256>>>(batch);
        attn_scatter_k<<<NN / 4, dim3(H, 4)>>>(batch);
    }

    // ---- 4. readout MLP ----
    feat_k<<<(NB * 130 + 255) / 256, 256>>>(t, p);
    launch_gemm(p_feat, W1, b1, nullptr, p_y1, NB, H, 130, 2);
    launch_gemm(p_y1, W2, b2, nullptr, p_y2, NB, H, H, 2);
    final_k<<<(NB + 255) / 256, 256>>>(W3, b3, (float*)d_out);
}

// round 3
// speedup vs baseline: 1.6358x; 1.6358x over previous
#include <cuda_runtime.h>
#include <cuda_fp16.h>
#include <cstddef>
#include <cstdint>

#define NN 20000      // nodes
#define NE 50000      // edges
#define NB 1024       // graphs
#define DIN 32
#define H 64

// ---------------- scratch (static device globals; no allocation) ----------------
__device__ float  g_out[NN * H];                    // node features (out == h)
__device__ float  g_z[NE * H];                      // edge hidden
__device__ __half g_ew[(size_t)NE * H * H];         // per-edge weight matrices (fp16, 410 MB)
__device__ float  g_agg[NN * H];
__device__ float  g_m[NN * H];
__device__ float  g_gi[NN * 3 * H];
__device__ float  g_gh[NN * 3 * H];
__device__ float  g_qh[NB * H];
__device__ float  g_qc[NB * H];
__device__ float  g_qstar[NB * 2 * H];
__device__ float  g_e[NN];
__device__ float  g_emax[NB];
__device__ float  g_asum[NB];

__device__ __forceinline__ float sigf(float x) { return 1.f / (1.f + __expf(-x)); }

__device__ __forceinline__ float atomicMaxFloat(float* addr, float value) {
    if (value >= 0.f)
        return __int_as_float(atomicMax((int*)addr, __float_as_int(value)));
    else
        return __uint_as_float(atomicMin((unsigned int*)addr, __float_as_uint(value)));
}

__device__ __forceinline__ unsigned f2tf32(float f) {
    unsigned u;
    asm("cvt.rna.tf32.f32 %0, %1;" : "=r"(u) : "f"(f));
    return u;
}

__device__ __forceinline__ void mma8(float* c, const unsigned* a, const unsigned* b) {
    asm volatile(
        "mma.sync.aligned.m16n8k8.row.col.f32.tf32.tf32.f32 "
        "{%0,%1,%2,%3},{%4,%5,%6,%7},{%8,%9},{%0,%1,%2,%3};"
        : "+f"(c[0]), "+f"(c[1]), "+f"(c[2]), "+f"(c[3])
        : "r"(a[0]), "r"(a[1]), "r"(a[2]), "r"(a[3]), "r"(b[0]), "r"(b[1]));
}

// ---------------- tf32 tensor-core GEMM, K fixed = 64 ----------------
// C[M,Nn] = A[M,64] @ B  (+bias, +add, relu).  BT: B stored as W[Nn,64] (C = A@W^T).
template<int BN, int WARPS_M, int WARPS_N, bool BT, bool RELU, bool HALF_OUT, bool ADD>
__global__ __launch_bounds__(256)
void mma_gemm(const float* __restrict__ A, const float* __restrict__ B,
              const float* __restrict__ bias, const float* __restrict__ add,
              void* __restrict__ Cv, int M, int Nn)
{
    constexpr int BM = 128, K = 64, ALD = 68, BLD = BN + 8;
    constexpr int WM = BM / WARPS_M, WN = BN / WARPS_N;
    constexpr int MT = WM / 16, NT = WN / 8;

    extern __shared__ unsigned sm_u[];
    unsigned* As = sm_u;                 // [BM][ALD]
    unsigned* Bs = sm_u + BM * ALD;      // [K][BLD]

    const int tid = threadIdx.x, warp = tid >> 5, lane = tid & 31;
    const int g = lane >> 2, t = lane & 3;
    const int wm = warp / WARPS_N, wn = warp % WARPS_N;
    const int m0 = blockIdx.y * BM, n0 = blockIdx.x * BN;

    // load A tile (128 x 64), cvt to tf32
#pragma unroll
    for (int i = 0; i < 8; i++) {
        int lin = i * 256 + tid;           // 2048 float4
        int row = lin >> 4, c4 = lin & 15;
        int gm = m0 + row;
        float4 v = make_float4(0.f, 0.f, 0.f, 0.f);
        if (gm < M) v = *(const float4*)(A + (size_t)gm * K + c4 * 4);
        unsigned* dst = As + row * ALD + c4 * 4;
        dst[0] = f2tf32(v.x); dst[1] = f2tf32(v.y);
        dst[2] = f2tf32(v.z); dst[3] = f2tf32(v.w);
    }
    // load B tile (64 x BN)
    if (!BT) {
        constexpr int ITER = (K * BN / 4) / 256;
#pragma unroll
        for (int i = 0; i < ITER; i++) {
            int lin = i * 256 + tid;
            int row = lin / (BN / 4), c4 = lin % (BN / 4);
            int gn = n0 + c4 * 4;
            float4 v = make_float4(0.f, 0.f, 0.f, 0.f);
            if (gn < Nn) v = *(const float4*)(B + (size_t)row * Nn + gn);
            unsigned* dst = Bs + row * BLD + c4 * 4;
            dst[0] = f2tf32(v.x); dst[1] = f2tf32(v.y);
            dst[2] = f2tf32(v.z); dst[3] = f2tf32(v.w);
        }
    } else {
        constexpr int ITER = (K * BN) / 256;
#pragma unroll
        for (int i = 0; i < ITER; i++) {
            int lin = i * 256 + tid;
            int n = lin >> 6, k = lin & 63;
            int gn = n0 + n;
            float v = (gn < Nn) ? B[(size_t)gn * K + k] : 0.f;
            Bs[k * BLD + n] = f2tf32(v);
        }
    }
    __syncthreads();

    float acc[MT][NT][4];
#pragma unroll
    for (int mt = 0; mt < MT; mt++)
#pragma unroll
        for (int nt = 0; nt < NT; nt++)
#pragma unroll
            for (int q = 0; q < 4; q++) acc[mt][nt][q] = 0.f;

#pragma unroll
    for (int kk = 0; kk < 8; kk++) {
        unsigned a[MT][4], b[NT][2];
#pragma unroll
        for (int mt = 0; mt < MT; mt++) {
            int rb = wm * WM + mt * 16;
            a[mt][0] = As[(rb + g) * ALD + kk * 8 + t];
            a[mt][1] = As[(rb + g + 8) * ALD + kk * 8 + t];
            a[mt][2] = As[(rb + g) * ALD + kk * 8 + t + 4];
            a[mt][3] = As[(rb + g + 8) * ALD + kk * 8 + t + 4];
        }
#pragma unroll
        for (int nt = 0; nt < NT; nt++) {
            int cb = wn * WN + nt * 8;
            b[nt][0] = Bs[(kk * 8 + t) * BLD + cb + g];
            b[nt][1] = Bs[(kk * 8 + t + 4) * BLD + cb + g];
        }
#pragma unroll
        for (int mt = 0; mt < MT; mt++)
#pragma unroll
            for (int nt = 0; nt < NT; nt++)
                mma8(acc[mt][nt], a[mt], b[nt]);
    }

    // epilogue
#pragma unroll
    for (int mt = 0; mt < MT; mt++) {
#pragma unroll
        for (int nt = 0; nt < NT; nt++) {
            int r0 = m0 + wm * WM + mt * 16 + g;
            int r1 = r0 + 8;
            int c0 = n0 + wn * WN + nt * 8 + 2 * t;
            float bv0 = bias[c0], bv1 = bias[c0 + 1];
#pragma unroll
            for (int half_ = 0; half_ < 2; half_++) {
                int r = half_ ? r1 : r0;
                if (r >= M) continue;
                float v0 = acc[mt][nt][half_ * 2 + 0] + bv0;
                float v1 = acc[mt][nt][half_ * 2 + 1] + bv1;
                if (ADD) {
                    v0 += add[(size_t)r * Nn + c0];
                    v1 += add[(size_t)r * Nn + c0 + 1];
                }
                if (RELU) { v0 = fmaxf(v0, 0.f); v1 = fmaxf(v1, 0.f); }
                if (HALF_OUT) {
                    *(__half2*)((__half*)Cv + (size_t)r * Nn + c0) = __floats2half2_rn(v0, v1);
                } else {
                    *(float2*)((float*)Cv + (size_t)r * Nn + c0) = make_float2(v0, v1);
                }
            }
        }
    }
}

// ---------------- fallback SIMT GEMM (small one-off matmuls: W0, We1) ----------
#define BM_S 128
#define BN_S 128
#define BK_S 64
#define ALD_S 68
#define BLD_S 132
#define GEMM_SMEM ((BM_S * ALD_S + BK_S * BLD_S) * 4)

__global__ __launch_bounds__(256)
void gemm_k(const float* __restrict__ A, const float* __restrict__ B,
            const float* __restrict__ bias, float* __restrict__ C,
            int M, int Nn, int K, int flags)
{
    extern __shared__ float sm[];
    float* As = sm;
    float* Bs = sm + BM_S * ALD_S;
    const bool dorelu = flags & 2;

    int tid = threadIdx.x;
    int m0 = blockIdx.y * BM_S, n0 = blockIdx.x * BN_S;
    int tx = tid & 15, ty = tid >> 4;
    int tm = ty * 8, tn = tx * 8;

    float acc[8][8];
#pragma unroll
    for (int i = 0; i < 8; i++)
#pragma unroll
        for (int j = 0; j < 8; j++) acc[i][j] = 0.f;

    for (int k0 = 0; k0 < K; k0 += BK_S) {
#pragma unroll
        for (int i = 0; i < 32; i++) {
            int lin = i * 256 + tid;
            int m = lin >> 6, k = lin & 63;
            int gm = m0 + m, gk = k0 + k;
            As[m * ALD_S + k] = (gm < M && gk < K) ? A[(size_t)gm * K + gk] : 0.f;
        }
#pragma unroll
        for (int i = 0; i < 32; i++) {
            int lin = i * 256 + tid;
            int k = lin >> 7, n = lin & 127;
            int gk = k0 + k, gn = n0 + n;
            Bs[k * BLD_S + n] = (gk < K && gn < Nn) ? B[(size_t)gk * Nn + gn] : 0.f;
        }
        __syncthreads();
#pragma unroll 8
        for (int k = 0; k < BK_S; k++) {
            float a[8], b[8];
#pragma unroll
            for (int i = 0; i < 8; i++) a[i] = As[(tm + i) * ALD_S + k];
            float4 bv0 = *(const float4*)&Bs[k * BLD_S + tn];
            float4 bv1 = *(const float4*)&Bs[k * BLD_S + tn + 4];
            b[0] = bv0.x; b[1] = bv0.y; b[2] = bv0.z; b[3] = bv0.w;
            b[4] = bv1.x; b[5] = bv1.y; b[6] = bv1.z; b[7] = bv1.w;
#pragma unroll
            for (int i = 0; i < 8; i++)
#pragma unroll
                for (int j = 0; j < 8; j++) acc[i][j] = fmaf(a[i], b[j], acc[i][j]);
        }
        __syncthreads();
    }
#pragma unroll
    for (int i = 0; i < 8; i++) {
        int gm = m0 + tm + i;
        if (gm >= M) continue;
#pragma unroll
        for (int j = 0; j < 8; j++) {
            int gn = n0 + tn + j;
            if (gn >= Nn) continue;
            float v = acc[i][j] + bias[gn];
            if (dorelu) v = fmaxf(v, 0.f);
            C[(size_t)gm * Nn + gn] = v;
        }
    }
}

// ---------------- misc kernels ----------------
__global__ void zero_k(float* p, int n) {
    int i = blockIdx.x * 256 + threadIdx.x;
    if (i < n) p[i] = 0.f;
}

// per-edge: msg[e] = out[src[e]] (1xH) @ ew[e] (HxH, fp16); atomic scatter into agg[dst[e]]
__global__ __launch_bounds__(256)
void einsum_scatter(const int* __restrict__ ei) {
    __shared__ float s[8][H];
    int ey = threadIdx.y;            // 0..7 edge within block
    int l = threadIdx.x;             // 0..31 lane
    int e = blockIdx.x * 8 + ey;
    int tid = ey * 32 + l;
    {
        int r = tid >> 5, c = tid & 31;
        int e2 = blockIdx.x * 8 + r;
        if (e2 < NE) {
            int src = ei[e2];
            s[r][c] = g_out[src * H + c];
            s[r][c + 32] = g_out[src * H + c + 32];
        }
    }
    __syncthreads();
    if (e >= NE) return;
    const __half2* w = (const __half2*)g_ew + (size_t)e * 2048 + l;
    float2 acc = make_float2(0.f, 0.f);
#pragma unroll
    for (int h2 = 0; h2 < H; h2++) {
        float sv = s[ey][h2];
        float2 wv = __half22float2(w[h2 * 32]);
        acc.x = fmaf(sv, wv.x, acc.x);
        acc.y = fmaf(sv, wv.y, acc.y);
    }
    int dst = ei[NE + e];
    atomicAdd(&g_agg[dst * H + 2 * l], acc.x);
    atomicAdd(&g_agg[dst * H + 2 * l + 1], acc.y);
}

__global__ void gru_gate_k() {
    int idx = blockIdx.x * 256 + threadIdx.x;
    if (idx >= NN * H) return;
    int n = idx >> 6, j = idx & 63;
    const float* gi = g_gi + n * (3 * H);
    const float* gh = g_gh + n * (3 * H);
    float r = sigf(gi[j] + gh[j]);
    float z = sigf(gi[H + j] + gh[H + j]);
    float nn = tanhf(gi[2 * H + j] + r * gh[2 * H + j]);
    float h = g_out[idx];
    g_out[idx] = (1.f - z) * nn + z * h;
}

// fused Set2Set LSTM step: gates GEMV + LSTM update + attn-state reset
__global__ __launch_bounds__(256)
void lstm_step_k(const float* __restrict__ lwih, const float* __restrict__ lwhh,
                 const float* __restrict__ lbih, const float* __restrict__ lbhh) {
    __shared__ float qs[4][2 * H];
    __shared__ float qhh[4][H];
    int gl = threadIdx.x >> 6;          // graph within block (0..3)
    int j = threadIdx.x & 63;
    int b = blockIdx.x * 4 + gl;
    qs[gl][j] = g_qstar[b * 2 * H + j];
    qs[gl][j + H] = g_qstar[b * 2 * H + H + j];
    qhh[gl][j] = g_qh[b * H + j];
    __syncthreads();
    float gate[4];
#pragma unroll
    for (int gt = 0; gt < 4; gt++) {
        int row = gt * H + j;
        float a = lbih[row] + lbhh[row];
        const float* wi = lwih + (size_t)row * (2 * H);
        const float* wh = lwhh + (size_t)row * H;
#pragma unroll 8
        for (int k = 0; k < 2 * H; k++) a = fmaf(wi[k], qs[gl][k], a);
#pragma unroll 8
        for (int k = 0; k < H; k++) a = fmaf(wh[k], qhh[gl][k], a);
        gate[gt] = a;
    }
    float ig = sigf(gate[0]);
    float fg = sigf(gate[1]);
    float gg = tanhf(gate[2]);
    float og = sigf(gate[3]);
    int idx = b * H + j;
    float c = fg * g_qc[idx] + ig * gg;
    g_qc[idx] = c;
    float hh = og * tanhf(c);
    g_qh[idx] = hh;
    g_qstar[b * 2 * H + j] = hh;         // q part
    g_qstar[b * 2 * H + H + j] = 0.f;    // r accumulator reset
    if (j == 0) { g_emax[b] = -3.0e38f; g_asum[b] = 0.f; }
}

__global__ void attn_e_max_k(const int* __restrict__ batch) {
    int n = blockIdx.x * 256 + threadIdx.x;
    if (n >= NN) return;
    int b = batch[n];
    const float* o = g_out + n * H;
    const float* q = g_qh + b * H;
    float acc = 0.f;
#pragma unroll
    for (int j = 0; j < H; j++) acc = fmaf(o[j], q[j], acc);
    g_e[n] = acc;
    atomicMaxFloat(&g_emax[b], acc);
}

__global__ void attn_exp_k(const int* __restrict__ batch) {
    int n = blockIdx.x * 256 + threadIdx.x;
    if (n >= NN) return;
    int b = batch[n];
    float a = __expf(g_e[n] - g_emax[b]);
    g_e[n] = a;
    atomicAdd(&g_asum[b], a);
}

__global__ void attn_scatter_k(const int* __restrict__ batch) {
    int n = blockIdx.x * 4 + threadIdx.y;
    int j = threadIdx.x;
    if (n >= NN) return;
    int b = batch[n];
    float coeff = g_e[n] / g_asum[b];
    atomicAdd(&g_qstar[b * 2 * H + H + j], coeff * g_out[n * H + j]);
}

// fused readout MLP: [qstar|t|p] -> 64 -> 64 -> 1
__global__ __launch_bounds__(64)
void readout_k(const float* __restrict__ t, const float* __restrict__ p,
               const float* __restrict__ W1, const float* __restrict__ b1,
               const float* __restrict__ W2, const float* __restrict__ b2,
               const float* __restrict__ W3, const float* __restrict__ b3,
               float* __restrict__ out) {
    __shared__ float feat[130];
    __shared__ float y1s[H];
    __shared__ float y2s[H];
    int b = blockIdx.x;
    int j = threadIdx.x;
    feat[j] = g_qstar[b * 128 + j];
    feat[64 + j] = g_qstar[b * 128 + 64 + j];
    if (j == 0) { feat[128] = t[b]; feat[129] = p[b]; }
    __syncthreads();
    float a = b1[j];
#pragma unroll 10
    for (int k = 0; k < 130; k++) a = fmaf(feat[k], W1[k * H + j], a);
    y1s[j] = fmaxf(a, 0.f);
    __syncthreads();
    a = b2[j];
#pragma unroll 8
    for (int k = 0; k < H; k++) a = fmaf(y1s[k], W2[k * H + j], a);
    y2s[j] = fmaxf(a, 0.f) * W3[j];
    __syncthreads();
    if (j == 0) {
        float s = b3[0];
#pragma unroll
        for (int k = 0; k < H; k++) s += y2s[k];
        out[b] = s;
    }
}

// ---------------- host ----------------
static void launch_zero(float* p, int n) { zero_k<<<(n + 255) / 256, 256>>>(p, n); }

extern "C" void kernel_launch(void* const* d_in, const int* in_sizes, int n_in,
                              void* d_out, int out_size)
{
    // ---- resolve input ordering ----
    const float *x, *ea, *t, *p;
    const float *W0, *b0, *We1, *be1, *We2, *be2, *Wroot, *bconv;
    const float *wih, *whh, *bih, *bhh, *lwih, *lwhh, *lbih, *lbhh;
    const float *W1, *b1, *W2, *b2, *W3, *b3;
    const int *ei, *batch;

    bool dictOrder = (in_sizes[1] == 2 * NE);
    if (dictOrder) {
        x = (const float*)d_in[0];
        ei = (const int*)d_in[1];
        ea = (const float*)d_in[2];
        batch = (const int*)d_in[3];
        t = (const float*)d_in[4];
        p = (const float*)d_in[5];
        int w = (in_sizes[6] == 1) ? 7 : 6;
        W0 = (const float*)d_in[w + 0];  b0 = (const float*)d_in[w + 1];
        We1 = (const float*)d_in[w + 2]; be1 = (const float*)d_in[w + 3];
        We2 = (const float*)d_in[w + 4]; be2 = (const float*)d_in[w + 5];
        Wroot = (const float*)d_in[w + 6]; bconv = (const float*)d_in[w + 7];
        wih = (const float*)d_in[w + 8];  whh = (const float*)d_in[w + 9];
        bih = (const float*)d_in[w + 10]; bhh = (const float*)d_in[w + 11];
        lwih = (const float*)d_in[w + 12]; lwhh = (const float*)d_in[w + 13];
        lbih = (const float*)d_in[w + 14]; lbhh = (const float*)d_in[w + 15];
        W1 = (const float*)d_in[w + 16]; b1 = (const float*)d_in[w + 17];
        W2 = (const float*)d_in[w + 18]; b2 = (const float*)d_in[w + 19];
        W3 = (const float*)d_in[w + 20]; b3 = (const float*)d_in[w + 21];
    } else {
        x = (const float*)d_in[0];
        ea = (const float*)d_in[1];
        t = (const float*)d_in[2];
        p = (const float*)d_in[3];
        W0 = (const float*)d_in[4];  b0 = (const float*)d_in[5];
        We1 = (const float*)d_in[6]; be1 = (const float*)d_in[7];
        We2 = (const float*)d_in[8]; be2 = (const float*)d_in[9];
        Wroot = (const float*)d_in[10]; bconv = (const float*)d_in[11];
        wih = (const float*)d_in[12]; whh = (const float*)d_in[13];
        bih = (const float*)d_in[14]; bhh = (const float*)d_in[15];
        lwih = (const float*)d_in[16]; lwhh = (const float*)d_in[17];
        lbih = (const float*)d_in[18]; lbhh = (const float*)d_in[19];
        W1 = (const float*)d_in[20]; b1 = (const float*)d_in[21];
        W2 = (const float*)d_in[22]; b2 = (const float*)d_in[23];
        W3 = (const float*)d_in[24]; b3 = (const float*)d_in[25];
        ei = (const int*)d_in[26];
        batch = (const int*)d_in[27];
    }

    // ---- scratch addresses ----
    float *p_out, *p_z, *p_agg, *p_m, *p_gi, *p_gh, *p_qh, *p_qc, *p_qstar;
    __half* p_ew;
    cudaGetSymbolAddress((void**)&p_out, g_out);
    cudaGetSymbolAddress((void**)&p_z, g_z);
    cudaGetSymbolAddress((void**)&p_ew, g_ew);
    cudaGetSymbolAddress((void**)&p_agg, g_agg);
    cudaGetSymbolAddress((void**)&p_m, g_m);
    cudaGetSymbolAddress((void**)&p_gi, g_gi);
    cudaGetSymbolAddress((void**)&p_gh, g_gh);
    cudaGetSymbolAddress((void**)&p_qh, g_qh);
    cudaGetSymbolAddress((void**)&p_qc, g_qc);
    cudaGetSymbolAddress((void**)&p_qstar, g_qstar);

    // mma kernel instantiations
    auto ew_kernel = mma_gemm<256, 2, 4, false, false, true, false>;   // ew = z@We2+be2 -> fp16
    auto gi_kernel = mma_gemm<64, 8, 1, true, false, false, false>;    // gi = m@wih^T + bih
    auto m_kernel  = mma_gemm<64, 8, 1, false, true, false, true>;     // m = relu(agg + out@Wroot + bconv)

    constexpr int SMEM_EW  = (128 * 68 + 64 * 264) * 4;
    constexpr int SMEM_GEN = (128 * 68 + 64 * 72) * 4;
    cudaFuncSetAttribute(ew_kernel, cudaFuncAttributeMaxDynamicSharedMemorySize, SMEM_EW);
    cudaFuncSetAttribute(gi_kernel, cudaFuncAttributeMaxDynamicSharedMemorySize, SMEM_GEN);
    cudaFuncSetAttribute(m_kernel,  cudaFuncAttributeMaxDynamicSharedMemorySize, SMEM_GEN);
    cudaFuncSetAttribute(gemm_k, cudaFuncAttributeMaxDynamicSharedMemorySize, GEMM_SMEM);

    // ---- 1. input linear + edge MLP ----
    {   // out = relu(x @ W0 + b0)   [20000,32]x[32,64]
        dim3 grid(1, (NN + 127) / 128);
        gemm_k<<<grid, 256, GEMM_SMEM>>>(x, W0, b0, p_out, NN, H, DIN, 2);
    }
    {   // z = relu(ea @ We1 + be1)  [50000,6]x[6,64]
        dim3 grid(1, (NE + 127) / 128);
        gemm_k<<<grid, 256, GEMM_SMEM>>>(ea, We1, be1, p_z, NE, H, 6, 2);
    }
    {   // ew = z @ We2 + be2        [50000,64]x[64,4096] -> fp16
        dim3 grid(4096 / 256, (NE + 127) / 128);
        ew_kernel<<<grid, 256, SMEM_EW>>>(p_z, We2, be2, nullptr, p_ew, NE, H * H);
    }

    // ---- 2. 4x (NNConv + GRU) ----
    for (int it = 0; it < 4; it++) {
        launch_zero(p_agg, NN * H);
        einsum_scatter<<<NE / 8, dim3(32, 8)>>>(ei);
        {   dim3 grid(1, (NN + 127) / 128);
            m_kernel<<<grid, 256, SMEM_GEN>>>(p_out, Wroot, bconv, p_agg, p_m, NN, H);
        }
        {   dim3 grid(3, (NN + 127) / 128);
            gi_kernel<<<grid, 256, SMEM_GEN>>>(p_m, wih, bih, nullptr, p_gi, NN, 3 * H);
            gi_kernel<<<grid, 256, SMEM_GEN>>>(p_out, whh, bhh, nullptr, p_gh, NN, 3 * H);
        }
        gru_gate_k<<<(NN * H + 255) / 256, 256>>>();
    }

    // ---- 3. Set2Set (3 steps) ----
    launch_zero(p_qh, NB * H);
    launch_zero(p_qc, NB * H);
    launch_zero(p_qstar, NB * 2 * H);
    for (int st = 0; st < 3; st++) {
        lstm_step_k<<<NB / 4, 256>>>(lwih, lwhh, lbih, lbhh);
        attn_e_max_k<<<(NN + 255) / 256, 256>>>(batch);
        attn_exp_k<<<(NN + 255) / 256, 256>>>(batch);
        attn_scatter_k<<<NN / 4, dim3(H, 4)>>>(batch);
    }

    // ---- 4. readout MLP (fused) ----
    readout_k<<<NB, 64>>>(t, p, W1, b1, W2, b2, W3, b3, (float*)d_out);
}